// round 10
// baseline (speedup 1.0000x reference)
#include <cuda_runtime.h>
#include <cuda_bf16.h>
#include <cstdint>

// VectorQuantizer: x[131072,64] f32, W[1024,64] f32.
// out = [quantized(N,64) | quantized(N,64) | indices-as-f32(N)]
// argmin_k ||f-w_k||^2 == argmax_k ( f.w_k - 0.5||w_k||^2 )
// mma.sync bf16, exact 3-way split, 6 product passes (hh,hm,mh,hl,lh,mm).
// R6: paired-ntile MMA scheduling (dep distance 2 -> 4) to close tensor idle.

#define NROWS   131072
#define DIM     64
#define NCODE   1024
#define MCTA    128
#define NCHUNK  64
#define NCHUNKS (NCODE / NCHUNK)
#define THREADS 256

#define ROWB    144                     // padded row stride (72 bf16)
#define SPLIT_A (MCTA * ROWB)           // 18432
#define SPLIT_B (NCHUNK * ROWB)         // 9216
#define BUF_B   (3 * SPLIT_B)           // 27648
#define SM_A    0
#define SM_B    (3 * SPLIT_A)           // 55296
#define SM_BIAS (SM_B + 2 * BUF_B)      // 110592
#define SMEM_TOTAL (SM_BIAS + 512)      // 111104

__device__ __align__(16) __nv_bfloat16 g_Wsplit[3][NCODE][DIM];
__device__ __align__(16) float g_bias[NCODE];

// ---- helpers ---------------------------------------------------------------
__device__ __forceinline__ uint32_t smem_to_u32(const void* p) {
    uint32_t a;
    asm("{ .reg .u64 t; cvta.to.shared.u64 t, %1; cvt.u32.u64 %0, t; }" : "=r"(a) : "l"(p));
    return a;
}
__device__ __forceinline__ void split3(float v, __nv_bfloat16& h, __nv_bfloat16& m, __nv_bfloat16& l) {
    h = __float2bfloat16_rn(v);
    float r1 = v - __bfloat162float(h);
    m = __float2bfloat16_rn(r1);
    float r2 = r1 - __bfloat162float(m);
    l = __float2bfloat16_rn(r2);
}
__device__ __forceinline__ uint32_t pack2(__nv_bfloat16 a, __nv_bfloat16 b) {
    __nv_bfloat162 t = __halves2bfloat162(a, b);
    return *reinterpret_cast<uint32_t*>(&t);
}
#define LDSM_X4(r0, r1, r2, r3, a) \
    asm volatile("ldmatrix.sync.aligned.m8n8.x4.shared.b16 {%0,%1,%2,%3}, [%4];" \
                 : "=r"(r0), "=r"(r1), "=r"(r2), "=r"(r3) : "r"(a))
#define MMA_BF16(d, a, b) \
    asm volatile("mma.sync.aligned.m16n8k16.row.col.f32.bf16.bf16.f32 " \
                 "{%0,%1,%2,%3}, {%4,%5,%6,%7}, {%8,%9}, {%0,%1,%2,%3};" \
                 : "+f"((d)[0]), "+f"((d)[1]), "+f"((d)[2]), "+f"((d)[3]) \
                 : "r"((a)[0]), "r"((a)[1]), "r"((a)[2]), "r"((a)[3]), "r"((b)[0]), "r"((b)[1]))
#define CP_ASYNC16(dst, src) \
    asm volatile("cp.async.cg.shared.global [%0], [%1], 16;" \
                 :: "r"((uint32_t)(dst)), "l"((size_t)__cvta_generic_to_global(src)) : "memory")
#define CP_COMMIT() asm volatile("cp.async.commit_group;" ::: "memory")
#define CP_WAIT(n)  asm volatile("cp.async.wait_group %0;" :: "n"(n) : "memory")

// ---- prep: split codebook + bias -------------------------------------------
__global__ void prep_kernel(const float* __restrict__ W) {
    int k = blockIdx.x * blockDim.x + threadIdx.x;
    if (k >= NCODE) return;
    float s = 0.0f;
#pragma unroll
    for (int d = 0; d < DIM; d++) {
        float v = W[(size_t)k * DIM + d];
        __nv_bfloat16 h, m, l;
        split3(v, h, m, l);
        g_Wsplit[0][k][d] = h; g_Wsplit[1][k][d] = m; g_Wsplit[2][k][d] = l;
        s = fmaf(v, v, s);
    }
    g_bias[k] = -0.5f * s;
}

// issue cp.async for B chunk `kbase` into buffer bsel
__device__ __forceinline__ void prefetch_chunk(uint32_t sbase, int bsel, int kbase, int tid) {
    const char* gw = reinterpret_cast<const char*>(g_Wsplit);
#pragma unroll
    for (int t = 0; t < 6; t++) {
        int i = tid + t * THREADS;                 // 0..1535
        int split = i >> 9, rem = i & 511, n = rem >> 3, ch = rem & 7;
        uint32_t dst = sbase + SM_B + bsel * BUF_B + split * SPLIT_B + n * ROWB + ch * 16;
        const char* src = gw + (((size_t)split * NCODE + kbase + n) * 8 + ch) * 16;
        CP_ASYNC16(dst, src);
    }
    if (tid < 16)
        CP_ASYNC16(sbase + SM_BIAS + bsel * 256 + tid * 16,
                   reinterpret_cast<const char*>(g_bias) + (size_t)kbase * 4 + tid * 16);
    CP_COMMIT();
}

// ---- main kernel ------------------------------------------------------------
__global__ __launch_bounds__(THREADS, 2)
void vq_kernel(const float* __restrict__ x,
               const float* __restrict__ W,
               float* __restrict__ out) {
    extern __shared__ char smem[];
    const uint32_t sbase = smem_to_u32(smem);
    const int tid  = threadIdx.x;
    const int lane = tid & 31;
    const int wid  = tid >> 5;
    const int wm   = wid * 16;          // 16 rows per warp, all 64 codes/chunk

    // kick off chunk 0 load before anything else
    prefetch_chunk(sbase, 0, 0, tid);

    // ---- stage A rows into smem (3-way split) -------------
    {
        const int row = tid >> 1, half = tid & 1;
        const float4* xr = reinterpret_cast<const float4*>(
            x + ((size_t)blockIdx.x * MCTA + row) * DIM + half * 32);
        char* a0 = smem + SM_A + row * ROWB + half * 64;
#pragma unroll
        for (int i = 0; i < 8; i++) {
            float4 v = xr[i];
            __nv_bfloat16 h0, m0, l0, h1, m1, l1, h2, m2, l2, h3, m3, l3;
            split3(v.x, h0, m0, l0); split3(v.y, h1, m1, l1);
            split3(v.z, h2, m2, l2); split3(v.w, h3, m3, l3);
            *reinterpret_cast<uint32_t*>(a0 + 0 * SPLIT_A + i * 8)     = pack2(h0, h1);
            *reinterpret_cast<uint32_t*>(a0 + 0 * SPLIT_A + i * 8 + 4) = pack2(h2, h3);
            *reinterpret_cast<uint32_t*>(a0 + 1 * SPLIT_A + i * 8)     = pack2(m0, m1);
            *reinterpret_cast<uint32_t*>(a0 + 1 * SPLIT_A + i * 8 + 4) = pack2(m2, m3);
            *reinterpret_cast<uint32_t*>(a0 + 2 * SPLIT_A + i * 8)     = pack2(l0, l1);
            *reinterpret_cast<uint32_t*>(a0 + 2 * SPLIT_A + i * 8 + 4) = pack2(l2, l3);
        }
    }
    __syncthreads();

    // ---- A fragments -> registers, persistent for all chunks ----
    uint32_t Af[3][4][4];
    {
        const uint32_t aB = sbase + SM_A + (uint32_t)(wm + (lane & 15)) * ROWB + (lane >> 4) * 16;
#pragma unroll
        for (int sa = 0; sa < 3; sa++)
#pragma unroll
            for (int k = 0; k < 4; k++)
                LDSM_X4(Af[sa][k][0], Af[sa][k][1], Af[sa][k][2], Af[sa][k][3],
                        aB + sa * SPLIT_A + k * 32);
    }

    float best[2] = {-3.0e38f, -3.0e38f};
    int   bidx[2] = {0, 0};

    // B ldmatrix base: x4 covers two n-tiles (codes n0..n0+7 and n0+8..n0+15)
    const uint32_t bb = sbase + SM_B
        + (uint32_t)(((lane >> 4) & 1) * 8 + (lane & 7)) * ROWB
        + ((lane >> 3) & 1) * 16;

    for (int c = 0; c < NCHUNKS; c++) {
        if (c + 1 < NCHUNKS) {
            prefetch_chunk(sbase, (c + 1) & 1, (c + 1) * NCHUNK, tid);
            CP_WAIT(1);
        } else {
            CP_WAIT(0);
        }
        __syncthreads();

        const float* sBias = reinterpret_cast<const float*>(smem + SM_BIAS + (c & 1) * 256);
        float acc[8][4];
#pragma unroll
        for (int nt = 0; nt < 8; nt++) {
            float2 b01 = *reinterpret_cast<const float2*>(&sBias[nt * 8 + (lane & 3) * 2]);
            acc[nt][0] = b01.x; acc[nt][1] = b01.y;
            acc[nt][2] = b01.x; acc[nt][3] = b01.y;
        }

        const uint32_t bbc = bb + (c & 1) * BUF_B;
#pragma unroll
        for (int k = 0; k < 4; k++) {
#pragma unroll
            for (int sb = 0; sb < 3; sb++) {
#pragma unroll
                for (int np = 0; np < 2; np++) {   // pairs of 16-wide n-tiles
                    uint32_t Bf0[4], Bf1[4];
                    uint32_t bB = bbc + sb * SPLIT_B + np * 32 * ROWB + k * 32;
                    LDSM_X4(Bf0[0], Bf0[1], Bf0[2], Bf0[3], bB);
                    LDSM_X4(Bf1[0], Bf1[1], Bf1[2], Bf1[3], bB + 16 * ROWB);
                    // 4 independent acc chains per sa step (dep distance 4)
#pragma unroll
                    for (int sa = 0; sa < 3 - sb; sa++) {
                        MMA_BF16(acc[4 * np + 0], Af[sa][k], Bf0);
                        MMA_BF16(acc[4 * np + 1], Af[sa][k], Bf0 + 2);
                        MMA_BF16(acc[4 * np + 2], Af[sa][k], Bf1);
                        MMA_BF16(acc[4 * np + 3], Af[sa][k], Bf1 + 2);
                    }
                }
            }
        }

        // argmax update: 2 row-chains per thread (rows lane>>2 and +8)
#pragma unroll
        for (int nt = 0; nt < 8; nt++)
#pragma unroll
            for (int q = 0; q < 2; q++)
#pragma unroll
                for (int e = 0; e < 2; e++) {
                    float v = acc[nt][q * 2 + e];
                    int n = c * NCHUNK + nt * 8 + (lane & 3) * 2 + e;
                    if (v > best[q]) { best[q] = v; bidx[q] = n; }
                }

        __syncthreads();   // buf (c&1) free for the c+2 prefetch
    }

    // ---- reduce across the 4 lanes sharing each row (cols) ----
#pragma unroll
    for (int q = 0; q < 2; q++) {
#pragma unroll
        for (int off = 1; off < 4; off <<= 1) {
            float ov = __shfl_xor_sync(0xFFFFFFFFu, best[q], off);
            int   oi = __shfl_xor_sync(0xFFFFFFFFu, bidx[q], off);
            if (ov > best[q] || (ov == best[q] && oi < bidx[q])) {
                best[q] = ov; bidx[q] = oi;
            }
        }
    }

    // ---- gather codewords + write outputs ----
    const int lq = lane & 3;   // dim slice lq*16 .. lq*16+15
#pragma unroll
    for (int q = 0; q < 2; q++) {
        const int r = wm + (lane >> 2) + q * 8;
        const size_t grow = (size_t)blockIdx.x * MCTA + r;
        const int K = bidx[q];
        const float4* wsrc = reinterpret_cast<const float4*>(W + (size_t)K * DIM + lq * 16);
        float4* o1 = reinterpret_cast<float4*>(out + grow * DIM + lq * 16);
        float4* o2 = reinterpret_cast<float4*>(out + ((size_t)NROWS + grow) * DIM + lq * 16);
#pragma unroll
        for (int i = 0; i < 4; i++) {
            float4 v = wsrc[i];
            o1[i] = v;
            o2[i] = v;
        }
        if (lq == 0)
            out[(size_t)2 * NROWS * DIM + grow] = (float)K;
    }
}

// ---- launch -----------------------------------------------------------------
extern "C" void kernel_launch(void* const* d_in, const int* in_sizes, int n_in,
                              void* d_out, int out_size) {
    const float* x = (const float*)d_in[0];
    const float* W = (const float*)d_in[1];
    float* out = (float*)d_out;

    cudaFuncSetAttribute(vq_kernel, cudaFuncAttributeMaxDynamicSharedMemorySize, SMEM_TOTAL);
    prep_kernel<<<NCODE / 256, 256>>>(W);
    vq_kernel<<<NROWS / MCTA, THREADS, SMEM_TOTAL>>>(x, W, out);
}

// round 11
// speedup vs baseline: 1.0011x; 1.0011x over previous
#include <cuda_runtime.h>
#include <cuda_bf16.h>
#include <cstdint>

// VectorQuantizer: x[131072,64] f32, W[1024,64] f32.
// out = [quantized(N,64) | quantized(N,64) | indices-as-f32(N)]
// argmin_k ||f-w_k||^2 == argmax_k ( f.w_k - 0.5||w_k||^2 )
// mma.sync bf16, exact 3-way split, 6 product passes (hh,hm,mh,hl,lh,mm).
// R6: paired-ntile MMA scheduling (dep distance 2 -> 4) to close tensor idle.

#define NROWS   131072
#define DIM     64
#define NCODE   1024
#define MCTA    128
#define NCHUNK  64
#define NCHUNKS (NCODE / NCHUNK)
#define THREADS 256

#define ROWB    144                     // padded row stride (72 bf16)
#define SPLIT_A (MCTA * ROWB)           // 18432
#define SPLIT_B (NCHUNK * ROWB)         // 9216
#define BUF_B   (3 * SPLIT_B)           // 27648
#define SM_A    0
#define SM_B    (3 * SPLIT_A)           // 55296
#define SM_BIAS (SM_B + 2 * BUF_B)      // 110592
#define SMEM_TOTAL (SM_BIAS + 512)      // 111104

__device__ __align__(16) __nv_bfloat16 g_Wsplit[3][NCODE][DIM];
__device__ __align__(16) float g_bias[NCODE];

// ---- helpers ---------------------------------------------------------------
__device__ __forceinline__ uint32_t smem_to_u32(const void* p) {
    uint32_t a;
    asm("{ .reg .u64 t; cvta.to.shared.u64 t, %1; cvt.u32.u64 %0, t; }" : "=r"(a) : "l"(p));
    return a;
}
__device__ __forceinline__ void split3(float v, __nv_bfloat16& h, __nv_bfloat16& m, __nv_bfloat16& l) {
    h = __float2bfloat16_rn(v);
    float r1 = v - __bfloat162float(h);
    m = __float2bfloat16_rn(r1);
    float r2 = r1 - __bfloat162float(m);
    l = __float2bfloat16_rn(r2);
}
__device__ __forceinline__ uint32_t pack2(__nv_bfloat16 a, __nv_bfloat16 b) {
    __nv_bfloat162 t = __halves2bfloat162(a, b);
    return *reinterpret_cast<uint32_t*>(&t);
}
#define LDSM_X4(r0, r1, r2, r3, a) \
    asm volatile("ldmatrix.sync.aligned.m8n8.x4.shared.b16 {%0,%1,%2,%3}, [%4];" \
                 : "=r"(r0), "=r"(r1), "=r"(r2), "=r"(r3) : "r"(a))
#define MMA_BF16(d, a, b) \
    asm volatile("mma.sync.aligned.m16n8k16.row.col.f32.bf16.bf16.f32 " \
                 "{%0,%1,%2,%3}, {%4,%5,%6,%7}, {%8,%9}, {%0,%1,%2,%3};" \
                 : "+f"((d)[0]), "+f"((d)[1]), "+f"((d)[2]), "+f"((d)[3]) \
                 : "r"((a)[0]), "r"((a)[1]), "r"((a)[2]), "r"((a)[3]), "r"((b)[0]), "r"((b)[1]))
#define CP_ASYNC16(dst, src) \
    asm volatile("cp.async.cg.shared.global [%0], [%1], 16;" \
                 :: "r"((uint32_t)(dst)), "l"((size_t)__cvta_generic_to_global(src)) : "memory")
#define CP_COMMIT() asm volatile("cp.async.commit_group;" ::: "memory")
#define CP_WAIT(n)  asm volatile("cp.async.wait_group %0;" :: "n"(n) : "memory")

// ---- prep: split codebook + bias -------------------------------------------
__global__ void prep_kernel(const float* __restrict__ W) {
    int k = blockIdx.x * blockDim.x + threadIdx.x;
    if (k >= NCODE) return;
    float s = 0.0f;
#pragma unroll
    for (int d = 0; d < DIM; d++) {
        float v = W[(size_t)k * DIM + d];
        __nv_bfloat16 h, m, l;
        split3(v, h, m, l);
        g_Wsplit[0][k][d] = h; g_Wsplit[1][k][d] = m; g_Wsplit[2][k][d] = l;
        s = fmaf(v, v, s);
    }
    g_bias[k] = -0.5f * s;
}

// issue cp.async for B chunk `kbase` into buffer bsel
__device__ __forceinline__ void prefetch_chunk(uint32_t sbase, int bsel, int kbase, int tid) {
    const char* gw = reinterpret_cast<const char*>(g_Wsplit);
#pragma unroll
    for (int t = 0; t < 6; t++) {
        int i = tid + t * THREADS;                 // 0..1535
        int split = i >> 9, rem = i & 511, n = rem >> 3, ch = rem & 7;
        uint32_t dst = sbase + SM_B + bsel * BUF_B + split * SPLIT_B + n * ROWB + ch * 16;
        const char* src = gw + (((size_t)split * NCODE + kbase + n) * 8 + ch) * 16;
        CP_ASYNC16(dst, src);
    }
    if (tid < 16)
        CP_ASYNC16(sbase + SM_BIAS + bsel * 256 + tid * 16,
                   reinterpret_cast<const char*>(g_bias) + (size_t)kbase * 4 + tid * 16);
    CP_COMMIT();
}

// ---- main kernel ------------------------------------------------------------
__global__ __launch_bounds__(THREADS, 2)
void vq_kernel(const float* __restrict__ x,
               const float* __restrict__ W,
               float* __restrict__ out) {
    extern __shared__ char smem[];
    const uint32_t sbase = smem_to_u32(smem);
    const int tid  = threadIdx.x;
    const int lane = tid & 31;
    const int wid  = tid >> 5;
    const int wm   = wid * 16;          // 16 rows per warp, all 64 codes/chunk

    // kick off chunk 0 load before anything else
    prefetch_chunk(sbase, 0, 0, tid);

    // ---- stage A rows into smem (3-way split) -------------
    {
        const int row = tid >> 1, half = tid & 1;
        const float4* xr = reinterpret_cast<const float4*>(
            x + ((size_t)blockIdx.x * MCTA + row) * DIM + half * 32);
        char* a0 = smem + SM_A + row * ROWB + half * 64;
#pragma unroll
        for (int i = 0; i < 8; i++) {
            float4 v = xr[i];
            __nv_bfloat16 h0, m0, l0, h1, m1, l1, h2, m2, l2, h3, m3, l3;
            split3(v.x, h0, m0, l0); split3(v.y, h1, m1, l1);
            split3(v.z, h2, m2, l2); split3(v.w, h3, m3, l3);
            *reinterpret_cast<uint32_t*>(a0 + 0 * SPLIT_A + i * 8)     = pack2(h0, h1);
            *reinterpret_cast<uint32_t*>(a0 + 0 * SPLIT_A + i * 8 + 4) = pack2(h2, h3);
            *reinterpret_cast<uint32_t*>(a0 + 1 * SPLIT_A + i * 8)     = pack2(m0, m1);
            *reinterpret_cast<uint32_t*>(a0 + 1 * SPLIT_A + i * 8 + 4) = pack2(m2, m3);
            *reinterpret_cast<uint32_t*>(a0 + 2 * SPLIT_A + i * 8)     = pack2(l0, l1);
            *reinterpret_cast<uint32_t*>(a0 + 2 * SPLIT_A + i * 8 + 4) = pack2(l2, l3);
        }
    }
    __syncthreads();

    // ---- A fragments -> registers, persistent for all chunks ----
    uint32_t Af[3][4][4];
    {
        const uint32_t aB = sbase + SM_A + (uint32_t)(wm + (lane & 15)) * ROWB + (lane >> 4) * 16;
#pragma unroll
        for (int sa = 0; sa < 3; sa++)
#pragma unroll
            for (int k = 0; k < 4; k++)
                LDSM_X4(Af[sa][k][0], Af[sa][k][1], Af[sa][k][2], Af[sa][k][3],
                        aB + sa * SPLIT_A + k * 32);
    }

    float best[2] = {-3.0e38f, -3.0e38f};
    int   bidx[2] = {0, 0};

    // B ldmatrix base: x4 covers two n-tiles (codes n0..n0+7 and n0+8..n0+15)
    const uint32_t bb = sbase + SM_B
        + (uint32_t)(((lane >> 4) & 1) * 8 + (lane & 7)) * ROWB
        + ((lane >> 3) & 1) * 16;

    for (int c = 0; c < NCHUNKS; c++) {
        if (c + 1 < NCHUNKS) {
            prefetch_chunk(sbase, (c + 1) & 1, (c + 1) * NCHUNK, tid);
            CP_WAIT(1);
        } else {
            CP_WAIT(0);
        }
        __syncthreads();

        const float* sBias = reinterpret_cast<const float*>(smem + SM_BIAS + (c & 1) * 256);
        float acc[8][4];
#pragma unroll
        for (int nt = 0; nt < 8; nt++) {
            float2 b01 = *reinterpret_cast<const float2*>(&sBias[nt * 8 + (lane & 3) * 2]);
            acc[nt][0] = b01.x; acc[nt][1] = b01.y;
            acc[nt][2] = b01.x; acc[nt][3] = b01.y;
        }

        const uint32_t bbc = bb + (c & 1) * BUF_B;
#pragma unroll
        for (int k = 0; k < 4; k++) {
#pragma unroll
            for (int sb = 0; sb < 3; sb++) {
#pragma unroll
                for (int np = 0; np < 2; np++) {   // pairs of 16-wide n-tiles
                    uint32_t Bf0[4], Bf1[4];
                    uint32_t bB = bbc + sb * SPLIT_B + np * 32 * ROWB + k * 32;
                    LDSM_X4(Bf0[0], Bf0[1], Bf0[2], Bf0[3], bB);
                    LDSM_X4(Bf1[0], Bf1[1], Bf1[2], Bf1[3], bB + 16 * ROWB);
                    // 4 independent acc chains per sa step (dep distance 4)
#pragma unroll
                    for (int sa = 0; sa < 3 - sb; sa++) {
                        MMA_BF16(acc[4 * np + 0], Af[sa][k], Bf0);
                        MMA_BF16(acc[4 * np + 1], Af[sa][k], Bf0 + 2);
                        MMA_BF16(acc[4 * np + 2], Af[sa][k], Bf1);
                        MMA_BF16(acc[4 * np + 3], Af[sa][k], Bf1 + 2);
                    }
                }
            }
        }

        // argmax update: 2 row-chains per thread (rows lane>>2 and +8)
#pragma unroll
        for (int nt = 0; nt < 8; nt++)
#pragma unroll
            for (int q = 0; q < 2; q++)
#pragma unroll
                for (int e = 0; e < 2; e++) {
                    float v = acc[nt][q * 2 + e];
                    int n = c * NCHUNK + nt * 8 + (lane & 3) * 2 + e;
                    if (v > best[q]) { best[q] = v; bidx[q] = n; }
                }

        __syncthreads();   // buf (c&1) free for the c+2 prefetch
    }

    // ---- reduce across the 4 lanes sharing each row (cols) ----
#pragma unroll
    for (int q = 0; q < 2; q++) {
#pragma unroll
        for (int off = 1; off < 4; off <<= 1) {
            float ov = __shfl_xor_sync(0xFFFFFFFFu, best[q], off);
            int   oi = __shfl_xor_sync(0xFFFFFFFFu, bidx[q], off);
            if (ov > best[q] || (ov == best[q] && oi < bidx[q])) {
                best[q] = ov; bidx[q] = oi;
            }
        }
    }

    // ---- gather codewords + write outputs ----
    const int lq = lane & 3;   // dim slice lq*16 .. lq*16+15
#pragma unroll
    for (int q = 0; q < 2; q++) {
        const int r = wm + (lane >> 2) + q * 8;
        const size_t grow = (size_t)blockIdx.x * MCTA + r;
        const int K = bidx[q];
        const float4* wsrc = reinterpret_cast<const float4*>(W + (size_t)K * DIM + lq * 16);
        float4* o1 = reinterpret_cast<float4*>(out + grow * DIM + lq * 16);
        float4* o2 = reinterpret_cast<float4*>(out + ((size_t)NROWS + grow) * DIM + lq * 16);
#pragma unroll
        for (int i = 0; i < 4; i++) {
            float4 v = wsrc[i];
            o1[i] = v;
            o2[i] = v;
        }
        if (lq == 0)
            out[(size_t)2 * NROWS * DIM + grow] = (float)K;
    }
}

// ---- launch -----------------------------------------------------------------
extern "C" void kernel_launch(void* const* d_in, const int* in_sizes, int n_in,
                              void* d_out, int out_size) {
    const float* x = (const float*)d_in[0];
    const float* W = (const float*)d_in[1];
    float* out = (float*)d_out;

    cudaFuncSetAttribute(vq_kernel, cudaFuncAttributeMaxDynamicSharedMemorySize, SMEM_TOTAL);
    prep_kernel<<<NCODE / 256, 256>>>(W);
    vq_kernel<<<NROWS / MCTA, THREADS, SMEM_TOTAL>>>(x, W, out);
}

// round 12
// speedup vs baseline: 1.0022x; 1.0011x over previous
#include <cuda_runtime.h>
#include <cuda_bf16.h>
#include <cstdint>

// VectorQuantizer: x[131072,64] f32, W[1024,64] f32.
// out = [quantized(N,64) | quantized(N,64) | indices-as-f32(N)]
// argmin_k ||f-w_k||^2 == argmax_k ( f.w_k - 0.5||w_k||^2 )
// mma.sync bf16, exact 3-way split, 6 product passes (hh,hm,mh,hl,lh,mm).
// R12: 128-code windows, ONE barrier per window, odd-window B buffer aliases
//      the dead A-staging region. Barriers/CTA: 32 -> 8.

#define NROWS   131072
#define DIM     64
#define NCODE   1024
#define MCTA    128
#define WINDOW  128
#define NWIN    (NCODE / WINDOW)        // 8
#define THREADS 256

#define ROWB    144                     // padded row stride (72 bf16)
#define SPLIT_A (MCTA * ROWB)           // 18432 per split (A)
#define SPLIT_W (WINDOW * ROWB)         // 18432 per split (B window)
#define BUF_W   (3 * SPLIT_W)           // 55296
// SM_A = 0 .. 55296 : A staging; aliased as B buffer for ODD windows.
#define SM_BUF1 55296                   // dedicated B buffer (EVEN windows)
#define SM_BIAS (SM_BUF1 + BUF_W)       // 110592, two 512B slots
#define SMEM_TOTAL (SM_BIAS + 1024)     // 111616

__device__ __align__(16) __nv_bfloat16 g_Wsplit[3][NCODE][DIM];
__device__ __align__(16) float g_bias[NCODE];

// ---- helpers ---------------------------------------------------------------
__device__ __forceinline__ uint32_t smem_to_u32(const void* p) {
    uint32_t a;
    asm("{ .reg .u64 t; cvta.to.shared.u64 t, %1; cvt.u32.u64 %0, t; }" : "=r"(a) : "l"(p));
    return a;
}
__device__ __forceinline__ void split3(float v, __nv_bfloat16& h, __nv_bfloat16& m, __nv_bfloat16& l) {
    h = __float2bfloat16_rn(v);
    float r1 = v - __bfloat162float(h);
    m = __float2bfloat16_rn(r1);
    float r2 = r1 - __bfloat162float(m);
    l = __float2bfloat16_rn(r2);
}
__device__ __forceinline__ uint32_t pack2(__nv_bfloat16 a, __nv_bfloat16 b) {
    __nv_bfloat162 t = __halves2bfloat162(a, b);
    return *reinterpret_cast<uint32_t*>(&t);
}
#define LDSM_X4(r0, r1, r2, r3, a) \
    asm volatile("ldmatrix.sync.aligned.m8n8.x4.shared.b16 {%0,%1,%2,%3}, [%4];" \
                 : "=r"(r0), "=r"(r1), "=r"(r2), "=r"(r3) : "r"(a))
#define MMA_BF16(d, a, b) \
    asm volatile("mma.sync.aligned.m16n8k16.row.col.f32.bf16.bf16.f32 " \
                 "{%0,%1,%2,%3}, {%4,%5,%6,%7}, {%8,%9}, {%0,%1,%2,%3};" \
                 : "+f"((d)[0]), "+f"((d)[1]), "+f"((d)[2]), "+f"((d)[3]) \
                 : "r"((a)[0]), "r"((a)[1]), "r"((a)[2]), "r"((a)[3]), "r"((b)[0]), "r"((b)[1]))
#define CP_ASYNC16(dst, src) \
    asm volatile("cp.async.cg.shared.global [%0], [%1], 16;" \
                 :: "r"((uint32_t)(dst)), "l"((size_t)__cvta_generic_to_global(src)) : "memory")
#define CP_COMMIT() asm volatile("cp.async.commit_group;" ::: "memory")
#define CP_WAIT0()  asm volatile("cp.async.wait_group 0;" ::: "memory")

// ---- prep: split codebook + bias -------------------------------------------
__global__ void prep_kernel(const float* __restrict__ W) {
    int k = blockIdx.x * blockDim.x + threadIdx.x;
    if (k >= NCODE) return;
    float s = 0.0f;
#pragma unroll
    for (int d = 0; d < DIM; d++) {
        float v = W[(size_t)k * DIM + d];
        __nv_bfloat16 h, m, l;
        split3(v, h, m, l);
        g_Wsplit[0][k][d] = h; g_Wsplit[1][k][d] = m; g_Wsplit[2][k][d] = l;
        s = fmaf(v, v, s);
    }
    g_bias[k] = -0.5f * s;
}

// issue cp.async for window w (codes [kbase, kbase+128))
// even w -> SM_BUF1, odd w -> A region (smem offset 0)
__device__ __forceinline__ void prefetch_win(uint32_t sbase, int w, int kbase, int tid) {
    const char* gw = reinterpret_cast<const char*>(g_Wsplit);
    const uint32_t base = sbase + (((w & 1) == 0) ? SM_BUF1 : 0);
#pragma unroll
    for (int t = 0; t < 12; t++) {
        int i = tid + t * THREADS;                 // 0..3071
        int split = i >> 10, rem = i & 1023;
        int n = rem >> 3, ch = rem & 7;
        uint32_t dst = base + split * SPLIT_W + n * ROWB + ch * 16;
        const char* src = gw + (((size_t)split * NCODE + kbase + n) * 8 + ch) * 16;
        CP_ASYNC16(dst, src);
    }
    if (tid < 32)
        CP_ASYNC16(sbase + SM_BIAS + (w & 1) * 512 + tid * 16,
                   reinterpret_cast<const char*>(g_bias) + (size_t)kbase * 4 + tid * 16);
    CP_COMMIT();
}

// ---- main kernel ------------------------------------------------------------
__global__ __launch_bounds__(THREADS, 2)
void vq_kernel(const float* __restrict__ x,
               const float* __restrict__ W,
               float* __restrict__ out) {
    extern __shared__ char smem[];
    const uint32_t sbase = smem_to_u32(smem);
    const int tid  = threadIdx.x;
    const int lane = tid & 31;
    const int wid  = tid >> 5;
    const int wm   = wid * 16;          // 16 rows per warp, all codes per window

    // window 0 -> dedicated buffer; safe to start before A staging
    prefetch_win(sbase, 0, 0, tid);

    // ---- stage A rows into smem region [0, 55296) (3-way split) ----
    {
        const int row = tid >> 1, half = tid & 1;
        const float4* xr = reinterpret_cast<const float4*>(
            x + ((size_t)blockIdx.x * MCTA + row) * DIM + half * 32);
        char* a0 = smem + row * ROWB + half * 64;
#pragma unroll
        for (int i = 0; i < 8; i++) {
            float4 v = xr[i];
            __nv_bfloat16 h0, m0, l0, h1, m1, l1, h2, m2, l2, h3, m3, l3;
            split3(v.x, h0, m0, l0); split3(v.y, h1, m1, l1);
            split3(v.z, h2, m2, l2); split3(v.w, h3, m3, l3);
            *reinterpret_cast<uint32_t*>(a0 + 0 * SPLIT_A + i * 8)     = pack2(h0, h1);
            *reinterpret_cast<uint32_t*>(a0 + 0 * SPLIT_A + i * 8 + 4) = pack2(h2, h3);
            *reinterpret_cast<uint32_t*>(a0 + 1 * SPLIT_A + i * 8)     = pack2(m0, m1);
            *reinterpret_cast<uint32_t*>(a0 + 1 * SPLIT_A + i * 8 + 4) = pack2(m2, m3);
            *reinterpret_cast<uint32_t*>(a0 + 2 * SPLIT_A + i * 8)     = pack2(l0, l1);
            *reinterpret_cast<uint32_t*>(a0 + 2 * SPLIT_A + i * 8 + 4) = pack2(l2, l3);
        }
    }
    __syncthreads();

    // ---- A fragments -> registers, persistent (A smem dead afterwards) ----
    uint32_t Af[3][4][4];
    {
        const uint32_t aB = sbase + (uint32_t)(wm + (lane & 15)) * ROWB + (lane >> 4) * 16;
#pragma unroll
        for (int sa = 0; sa < 3; sa++)
#pragma unroll
            for (int k = 0; k < 4; k++)
                LDSM_X4(Af[sa][k][0], Af[sa][k][1], Af[sa][k][2], Af[sa][k][3],
                        aB + sa * SPLIT_A + k * 32);
    }

    float best[2] = {-3.0e38f, -3.0e38f};
    int   bidx[2] = {0, 0};

    // B ldmatrix lane offset: x4 covers two 8-wide n-tiles
    const uint32_t blane = (uint32_t)(((lane >> 4) & 1) * 8 + (lane & 7)) * ROWB
                         + ((lane >> 3) & 1) * 16;

    for (int w = 0; w < NWIN; w++) {
        CP_WAIT0();          // this window's buffer filled (own copies)
        __syncthreads();     // publish all threads' copies; all reads of the
                             // other buffer (window w-1, and A frags) are done
        if (w + 1 < NWIN)
            prefetch_win(sbase, w + 1, (w + 1) * WINDOW, tid);

        const uint32_t bufb = sbase + (((w & 1) == 0) ? SM_BUF1 : 0);
        const float* sBias = reinterpret_cast<const float*>(smem + SM_BIAS + (w & 1) * 512);

#pragma unroll
        for (int sc = 0; sc < 2; sc++) {       // two 64-code sub-chunks
            float acc[8][4];
#pragma unroll
            for (int nt = 0; nt < 8; nt++) {
                float2 b01 = *reinterpret_cast<const float2*>(
                    &sBias[sc * 64 + nt * 8 + (lane & 3) * 2]);
                acc[nt][0] = b01.x; acc[nt][1] = b01.y;
                acc[nt][2] = b01.x; acc[nt][3] = b01.y;
            }

            const uint32_t bbc = bufb + sc * 64 * ROWB + blane;
#pragma unroll
            for (int k = 0; k < 4; k++) {
#pragma unroll
                for (int sb = 0; sb < 3; sb++) {
#pragma unroll
                    for (int np = 0; np < 2; np++) {
                        uint32_t Bf0[4], Bf1[4];
                        uint32_t bB = bbc + sb * SPLIT_W + np * 32 * ROWB + k * 32;
                        LDSM_X4(Bf0[0], Bf0[1], Bf0[2], Bf0[3], bB);
                        LDSM_X4(Bf1[0], Bf1[1], Bf1[2], Bf1[3], bB + 16 * ROWB);
#pragma unroll
                        for (int sa = 0; sa < 3 - sb; sa++) {
                            MMA_BF16(acc[4 * np + 0], Af[sa][k], Bf0);
                            MMA_BF16(acc[4 * np + 1], Af[sa][k], Bf0 + 2);
                            MMA_BF16(acc[4 * np + 2], Af[sa][k], Bf1);
                            MMA_BF16(acc[4 * np + 3], Af[sa][k], Bf1 + 2);
                        }
                    }
                }
            }

            // argmax update: 2 row-chains per thread
            const int nbase = w * WINDOW + sc * 64;
#pragma unroll
            for (int nt = 0; nt < 8; nt++)
#pragma unroll
                for (int q = 0; q < 2; q++)
#pragma unroll
                    for (int e = 0; e < 2; e++) {
                        float v = acc[nt][q * 2 + e];
                        int n = nbase + nt * 8 + (lane & 3) * 2 + e;
                        if (v > best[q]) { best[q] = v; bidx[q] = n; }
                    }
        }
    }

    // ---- reduce across the 4 lanes sharing each row ----
#pragma unroll
    for (int q = 0; q < 2; q++) {
#pragma unroll
        for (int off = 1; off < 4; off <<= 1) {
            float ov = __shfl_xor_sync(0xFFFFFFFFu, best[q], off);
            int   oi = __shfl_xor_sync(0xFFFFFFFFu, bidx[q], off);
            if (ov > best[q] || (ov == best[q] && oi < bidx[q])) {
                best[q] = ov; bidx[q] = oi;
            }
        }
    }

    // ---- gather codewords + write outputs ----
    const int lq = lane & 3;   // dim slice lq*16 .. lq*16+15
#pragma unroll
    for (int q = 0; q < 2; q++) {
        const int r = wm + (lane >> 2) + q * 8;
        const size_t grow = (size_t)blockIdx.x * MCTA + r;
        const int K = bidx[q];
        const float4* wsrc = reinterpret_cast<const float4*>(W + (size_t)K * DIM + lq * 16);
        float4* o1 = reinterpret_cast<float4*>(out + grow * DIM + lq * 16);
        float4* o2 = reinterpret_cast<float4*>(out + ((size_t)NROWS + grow) * DIM + lq * 16);
#pragma unroll
        for (int i = 0; i < 4; i++) {
            float4 v = wsrc[i];
            o1[i] = v;
            o2[i] = v;
        }
        if (lq == 0)
            out[(size_t)2 * NROWS * DIM + grow] = (float)K;
    }
}

// ---- launch -----------------------------------------------------------------
extern "C" void kernel_launch(void* const* d_in, const int* in_sizes, int n_in,
                              void* d_out, int out_size) {
    const float* x = (const float*)d_in[0];
    const float* W = (const float*)d_in[1];
    float* out = (float*)d_out;

    cudaFuncSetAttribute(vq_kernel, cudaFuncAttributeMaxDynamicSharedMemorySize, SMEM_TOTAL);
    prep_kernel<<<NCODE / 256, 256>>>(W);
    vq_kernel<<<NROWS / MCTA, THREADS, SMEM_TOTAL>>>(x, W, out);
}

// round 13
// speedup vs baseline: 1.2361x; 1.2334x over previous
#include <cuda_runtime.h>
#include <cuda_bf16.h>
#include <cstdint>

// VectorQuantizer: x[131072,64] f32, W[1024,64] f32.
// out = [quantized(N,64) | quantized(N,64) | indices-as-f32(N)]
// argmin_k ||f-w_k||^2 == argmax_k ( f.w_k - 0.5||w_k||^2 )
// R13: two-phase. Phase 1: bf16 split passes hh,hm,mh (3 of 6) -> approx
//      scores, track top-2 per row. Phase 2: exact fp32 rescore of the 2
//      candidates. Tensor work halved vs 6-pass.

#define NROWS   131072
#define DIM     64
#define NCODE   1024
#define MCTA    128
#define WINDOW  128
#define NWIN    (NCODE / WINDOW)        // 8
#define THREADS 256

#define ROWB    144                     // padded row stride (72 bf16)
#define SPLIT_A (MCTA * ROWB)           // 18432 per split
#define SPLIT_W (WINDOW * ROWB)         // 18432 per split
#define BUF_W   (2 * SPLIT_W)           // 36864 (h,m splits only)
// [0, 36864)        : A staging (2 splits); aliased as B buffer for ODD windows
#define SM_BUF1 36864                   // B buffer for EVEN windows
#define SM_BIAS (SM_BUF1 + BUF_W)       // 73728, two 512B slots
#define SMEM_TOTAL (SM_BIAS + 1024)     // 74752

__device__ __align__(16) __nv_bfloat16 g_Wsplit[2][NCODE][DIM];   // h, m
__device__ __align__(16) float g_bias[NCODE];                     // -0.5||w||^2

// ---- helpers ---------------------------------------------------------------
__device__ __forceinline__ uint32_t smem_to_u32(const void* p) {
    uint32_t a;
    asm("{ .reg .u64 t; cvta.to.shared.u64 t, %1; cvt.u32.u64 %0, t; }" : "=r"(a) : "l"(p));
    return a;
}
__device__ __forceinline__ void split2(float v, __nv_bfloat16& h, __nv_bfloat16& m) {
    h = __float2bfloat16_rn(v);
    m = __float2bfloat16_rn(v - __bfloat162float(h));
}
__device__ __forceinline__ uint32_t pack2(__nv_bfloat16 a, __nv_bfloat16 b) {
    __nv_bfloat162 t = __halves2bfloat162(a, b);
    return *reinterpret_cast<uint32_t*>(&t);
}
__device__ __forceinline__ bool beats(float av, int ai, float bv, int bi) {
    return av > bv || (av == bv && ai < bi);
}
#define LDSM_X4(r0, r1, r2, r3, a) \
    asm volatile("ldmatrix.sync.aligned.m8n8.x4.shared.b16 {%0,%1,%2,%3}, [%4];" \
                 : "=r"(r0), "=r"(r1), "=r"(r2), "=r"(r3) : "r"(a))
#define MMA_BF16(d, a, b) \
    asm volatile("mma.sync.aligned.m16n8k16.row.col.f32.bf16.bf16.f32 " \
                 "{%0,%1,%2,%3}, {%4,%5,%6,%7}, {%8,%9}, {%0,%1,%2,%3};" \
                 : "+f"((d)[0]), "+f"((d)[1]), "+f"((d)[2]), "+f"((d)[3]) \
                 : "r"((a)[0]), "r"((a)[1]), "r"((a)[2]), "r"((a)[3]), "r"((b)[0]), "r"((b)[1]))
#define CP_ASYNC16(dst, src) \
    asm volatile("cp.async.cg.shared.global [%0], [%1], 16;" \
                 :: "r"((uint32_t)(dst)), "l"((size_t)__cvta_generic_to_global(src)) : "memory")
#define CP_COMMIT() asm volatile("cp.async.commit_group;" ::: "memory")
#define CP_WAIT0()  asm volatile("cp.async.wait_group 0;" ::: "memory")

// ---- prep: split codebook (h,m) + fp32 bias ---------------------------------
__global__ void prep_kernel(const float* __restrict__ W) {
    int k = blockIdx.x * blockDim.x + threadIdx.x;
    if (k >= NCODE) return;
    float s = 0.0f;
#pragma unroll
    for (int d = 0; d < DIM; d++) {
        float v = W[(size_t)k * DIM + d];
        __nv_bfloat16 h, m;
        split2(v, h, m);
        g_Wsplit[0][k][d] = h; g_Wsplit[1][k][d] = m;
        s = fmaf(v, v, s);
    }
    g_bias[k] = -0.5f * s;
}

// issue cp.async for window w (codes [kbase, kbase+128)), 2 splits
// even w -> SM_BUF1, odd w -> A region (offset 0)
__device__ __forceinline__ void prefetch_win(uint32_t sbase, int w, int kbase, int tid) {
    const char* gw = reinterpret_cast<const char*>(g_Wsplit);
    const uint32_t base = sbase + (((w & 1) == 0) ? SM_BUF1 : 0);
#pragma unroll
    for (int t = 0; t < 8; t++) {
        int i = tid + t * THREADS;                 // 0..2047
        int split = i >> 10, rem = i & 1023;
        int n = rem >> 3, ch = rem & 7;
        uint32_t dst = base + split * SPLIT_W + n * ROWB + ch * 16;
        const char* src = gw + (((size_t)split * NCODE + kbase + n) * 8 + ch) * 16;
        CP_ASYNC16(dst, src);
    }
    if (tid < 32)
        CP_ASYNC16(sbase + SM_BIAS + (w & 1) * 512 + tid * 16,
                   reinterpret_cast<const char*>(g_bias) + (size_t)kbase * 4 + tid * 16);
    CP_COMMIT();
}

// ---- main kernel ------------------------------------------------------------
__global__ __launch_bounds__(THREADS, 2)
void vq_kernel(const float* __restrict__ x,
               const float* __restrict__ W,
               float* __restrict__ out) {
    extern __shared__ char smem[];
    const uint32_t sbase = smem_to_u32(smem);
    const int tid  = threadIdx.x;
    const int lane = tid & 31;
    const int wid  = tid >> 5;
    const int wm   = wid * 16;          // 16 rows per warp

    prefetch_win(sbase, 0, 0, tid);     // window 0 -> dedicated buffer

    // ---- stage A rows into [0, 36864) (h,m splits) ----
    {
        const int row = tid >> 1, half = tid & 1;
        const float4* xr = reinterpret_cast<const float4*>(
            x + ((size_t)blockIdx.x * MCTA + row) * DIM + half * 32);
        char* a0 = smem + row * ROWB + half * 64;
#pragma unroll
        for (int i = 0; i < 8; i++) {
            float4 v = xr[i];
            __nv_bfloat16 h0, m0, h1, m1, h2, m2, h3, m3;
            split2(v.x, h0, m0); split2(v.y, h1, m1);
            split2(v.z, h2, m2); split2(v.w, h3, m3);
            *reinterpret_cast<uint32_t*>(a0 + i * 8)               = pack2(h0, h1);
            *reinterpret_cast<uint32_t*>(a0 + i * 8 + 4)           = pack2(h2, h3);
            *reinterpret_cast<uint32_t*>(a0 + SPLIT_A + i * 8)     = pack2(m0, m1);
            *reinterpret_cast<uint32_t*>(a0 + SPLIT_A + i * 8 + 4) = pack2(m2, m3);
        }
    }
    __syncthreads();

    // ---- A fragments (h,m) -> registers, persistent ----
    uint32_t Af[2][4][4];
    {
        const uint32_t aB = sbase + (uint32_t)(wm + (lane & 15)) * ROWB + (lane >> 4) * 16;
#pragma unroll
        for (int sa = 0; sa < 2; sa++)
#pragma unroll
            for (int k = 0; k < 4; k++)
                LDSM_X4(Af[sa][k][0], Af[sa][k][1], Af[sa][k][2], Af[sa][k][3],
                        aB + sa * SPLIT_A + k * 32);
    }

    // top-2 per row-chain (q=0: row wm+(lane>>2), q=1: +8)
    float b1[2] = {-3.0e38f, -3.0e38f}, b2[2] = {-3.0e38f, -3.0e38f};
    int   i1[2] = {0, 0},               i2[2] = {1, 1};

    const uint32_t blane = (uint32_t)(((lane >> 4) & 1) * 8 + (lane & 7)) * ROWB
                         + ((lane >> 3) & 1) * 16;

    for (int w = 0; w < NWIN; w++) {
        CP_WAIT0();
        __syncthreads();
        if (w + 1 < NWIN)
            prefetch_win(sbase, w + 1, (w + 1) * WINDOW, tid);

        const uint32_t bufb = sbase + (((w & 1) == 0) ? SM_BUF1 : 0);
        const float* sBias = reinterpret_cast<const float*>(smem + SM_BIAS + (w & 1) * 512);

#pragma unroll
        for (int sc = 0; sc < 2; sc++) {       // two 64-code sub-chunks
            float acc[8][4];
#pragma unroll
            for (int nt = 0; nt < 8; nt++) {
                float2 bb = *reinterpret_cast<const float2*>(
                    &sBias[sc * 64 + nt * 8 + (lane & 3) * 2]);
                acc[nt][0] = bb.x; acc[nt][1] = bb.y;
                acc[nt][2] = bb.x; acc[nt][3] = bb.y;
            }

            const uint32_t bbc = bufb + sc * 64 * ROWB + blane;
#pragma unroll
            for (int k = 0; k < 4; k++) {
#pragma unroll
                for (int np = 0; np < 2; np++) {
                    uint32_t Bh0[4], Bh1[4], Bm0[4], Bm1[4];
                    uint32_t bB = bbc + np * 32 * ROWB + k * 32;
                    LDSM_X4(Bh0[0], Bh0[1], Bh0[2], Bh0[3], bB);
                    LDSM_X4(Bh1[0], Bh1[1], Bh1[2], Bh1[3], bB + 16 * ROWB);
                    LDSM_X4(Bm0[0], Bm0[1], Bm0[2], Bm0[3], bB + SPLIT_W);
                    LDSM_X4(Bm1[0], Bm1[1], Bm1[2], Bm1[3], bB + SPLIT_W + 16 * ROWB);
                    // hh pass
                    MMA_BF16(acc[4 * np + 0], Af[0][k], Bh0);
                    MMA_BF16(acc[4 * np + 1], Af[0][k], Bh0 + 2);
                    MMA_BF16(acc[4 * np + 2], Af[0][k], Bh1);
                    MMA_BF16(acc[4 * np + 3], Af[0][k], Bh1 + 2);
                    // mh pass
                    MMA_BF16(acc[4 * np + 0], Af[1][k], Bh0);
                    MMA_BF16(acc[4 * np + 1], Af[1][k], Bh0 + 2);
                    MMA_BF16(acc[4 * np + 2], Af[1][k], Bh1);
                    MMA_BF16(acc[4 * np + 3], Af[1][k], Bh1 + 2);
                    // hm pass
                    MMA_BF16(acc[4 * np + 0], Af[0][k], Bm0);
                    MMA_BF16(acc[4 * np + 1], Af[0][k], Bm0 + 2);
                    MMA_BF16(acc[4 * np + 2], Af[0][k], Bm1);
                    MMA_BF16(acc[4 * np + 3], Af[0][k], Bm1 + 2);
                }
            }

            // top-2 update (scores arrive in increasing n per chain)
            const int nbase = w * WINDOW + sc * 64;
#pragma unroll
            for (int nt = 0; nt < 8; nt++)
#pragma unroll
                for (int q = 0; q < 2; q++)
#pragma unroll
                    for (int e = 0; e < 2; e++) {
                        float v = acc[nt][q * 2 + e];
                        int n = nbase + nt * 8 + (lane & 3) * 2 + e;
                        if (v > b1[q]) {
                            b2[q] = b1[q]; i2[q] = i1[q];
                            b1[q] = v;     i1[q] = n;
                        } else if (v > b2[q]) {
                            b2[q] = v;     i2[q] = n;
                        }
                    }
        }
    }

    // ---- quad merge: global top-2 per row across the 4 lanes ----
#pragma unroll
    for (int q = 0; q < 2; q++) {
#pragma unroll
        for (int off = 1; off < 4; off <<= 1) {
            float ob1 = __shfl_xor_sync(0xFFFFFFFFu, b1[q], off);
            int   oi1 = __shfl_xor_sync(0xFFFFFFFFu, i1[q], off);
            float ob2 = __shfl_xor_sync(0xFFFFFFFFu, b2[q], off);
            int   oi2 = __shfl_xor_sync(0xFFFFFFFFu, i2[q], off);
            bool ow = beats(ob1, oi1, b1[q], i1[q]);
            float nv1 = ow ? ob1 : b1[q];  int ni1 = ow ? oi1 : i1[q];
            float cv  = ow ? b1[q] : ob1;  int ci  = ow ? i1[q] : oi1;   // loser of tops
            float sv  = ow ? ob2 : b2[q];  int si  = ow ? oi2 : i2[q];   // winner's 2nd
            bool cw = beats(cv, ci, sv, si);
            b1[q] = nv1; i1[q] = ni1;
            b2[q] = cw ? cv : sv; i2[q] = cw ? ci : si;
        }
    }

    // ---- exact fp32 rescore of the two candidates ----
    int Kf[2];
#pragma unroll
    for (int q = 0; q < 2; q++) {
        const int r = wm + (lane >> 2) + q * 8;
        const size_t grow = (size_t)blockIdx.x * MCTA + r;
        const int c1 = i1[q], c2 = i2[q];
        float d1 = 0.0f, d2 = 0.0f;
#pragma unroll
        for (int k = 0; k < 4; k++)
#pragma unroll
            for (int ch = 0; ch < 2; ch++) {
                const int c0 = 2 * (lane & 3) + ch * 8 + 16 * k;
                float2 xx = *reinterpret_cast<const float2*>(x + grow * DIM + c0);
                float2 w1 = __ldg(reinterpret_cast<const float2*>(W + (size_t)c1 * DIM + c0));
                float2 w2 = __ldg(reinterpret_cast<const float2*>(W + (size_t)c2 * DIM + c0));
                d1 = fmaf(xx.x, w1.x, fmaf(xx.y, w1.y, d1));
                d2 = fmaf(xx.x, w2.x, fmaf(xx.y, w2.y, d2));
            }
        d1 += __shfl_xor_sync(0xFFFFFFFFu, d1, 1);
        d1 += __shfl_xor_sync(0xFFFFFFFFu, d1, 2);
        d2 += __shfl_xor_sync(0xFFFFFFFFu, d2, 1);
        d2 += __shfl_xor_sync(0xFFFFFFFFu, d2, 2);
        float s1 = d1 + __ldg(&g_bias[c1]);
        float s2 = d2 + __ldg(&g_bias[c2]);
        Kf[q] = beats(s1, c1, s2, c2) ? c1 : c2;
    }

    // ---- gather codewords + write outputs ----
    const int lq = lane & 3;   // dim slice lq*16 .. lq*16+15
#pragma unroll
    for (int q = 0; q < 2; q++) {
        const int r = wm + (lane >> 2) + q * 8;
        const size_t grow = (size_t)blockIdx.x * MCTA + r;
        const int K = Kf[q];
        const float4* wsrc = reinterpret_cast<const float4*>(W + (size_t)K * DIM + lq * 16);
        float4* o1 = reinterpret_cast<float4*>(out + grow * DIM + lq * 16);
        float4* o2 = reinterpret_cast<float4*>(out + ((size_t)NROWS + grow) * DIM + lq * 16);
#pragma unroll
        for (int i = 0; i < 4; i++) {
            float4 v = wsrc[i];
            o1[i] = v;
            o2[i] = v;
        }
        if (lq == 0)
            out[(size_t)2 * NROWS * DIM + grow] = (float)K;
    }
}

// ---- launch -----------------------------------------------------------------
extern "C" void kernel_launch(void* const* d_in, const int* in_sizes, int n_in,
                              void* d_out, int out_size) {
    const float* x = (const float*)d_in[0];
    const float* W = (const float*)d_in[1];
    float* out = (float*)d_out;

    cudaFuncSetAttribute(vq_kernel, cudaFuncAttributeMaxDynamicSharedMemorySize, SMEM_TOTAL);
    prep_kernel<<<NCODE / 256, 256>>>(W);
    vq_kernel<<<NROWS / MCTA, THREADS, SMEM_TOTAL>>>(x, W, out);
}

// round 14
// speedup vs baseline: 1.5119x; 1.2231x over previous
#include <cuda_runtime.h>
#include <cuda_bf16.h>
#include <cstdint>

// VectorQuantizer: x[131072,64] f32, W[1024,64] f32.
// out = [quantized(N,64) | quantized(N,64) | indices-as-f32(N)]
// argmin_k ||f-w_k||^2 == argmax_k ( f.w_k - 0.5||w_k||^2 )
// R14: phase-1 bf16 3-pass screening (hh,hm,mh) with BRANCHLESS keyed top-2
//      (4-bit local id in mantissa, FMNMX tournament); phase-2 exact fp32
//      rescore of the 2 candidates.

#define NROWS   131072
#define DIM     64
#define NCODE   1024
#define MCTA    128
#define WINDOW  128
#define NWIN    (NCODE / WINDOW)        // 8
#define THREADS 256

#define ROWB    144                     // padded row stride (72 bf16)
#define SPLIT_A (MCTA * ROWB)           // 18432 per split
#define SPLIT_W (WINDOW * ROWB)         // 18432 per split
#define BUF_W   (2 * SPLIT_W)           // 36864 (h,m splits)
// [0, 36864) : A staging (2 splits); aliased as B buffer for ODD windows
#define SM_BUF1 36864                   // B buffer for EVEN windows
#define SM_BIAS (SM_BUF1 + BUF_W)       // 73728, two 512B slots
#define SMEM_TOTAL (SM_BIAS + 1024)     // 74752

__device__ __align__(16) __nv_bfloat16 g_Wsplit[2][NCODE][DIM];   // h, m
__device__ __align__(16) float g_bias[NCODE];                     // -0.5||w||^2

// ---- helpers ---------------------------------------------------------------
__device__ __forceinline__ uint32_t smem_to_u32(const void* p) {
    uint32_t a;
    asm("{ .reg .u64 t; cvta.to.shared.u64 t, %1; cvt.u32.u64 %0, t; }" : "=r"(a) : "l"(p));
    return a;
}
__device__ __forceinline__ void split2(float v, __nv_bfloat16& h, __nv_bfloat16& m) {
    h = __float2bfloat16_rn(v);
    m = __float2bfloat16_rn(v - __bfloat162float(h));
}
__device__ __forceinline__ uint32_t pack2(__nv_bfloat16 a, __nv_bfloat16 b) {
    __nv_bfloat162 t = __halves2bfloat162(a, b);
    return *reinterpret_cast<uint32_t*>(&t);
}
__device__ __forceinline__ bool beats(float av, int ai, float bv, int bi) {
    return av > bv || (av == bv && ai < bi);
}
// embed 4-bit local id into low mantissa bits (order-preserving to 16 ulps)
__device__ __forceinline__ float embed4(float v, int lid) {
    return __uint_as_float((__float_as_uint(v) & 0xFFFFFFF0u) | (uint32_t)lid);
}
#define LDSM_X4(r0, r1, r2, r3, a) \
    asm volatile("ldmatrix.sync.aligned.m8n8.x4.shared.b16 {%0,%1,%2,%3}, [%4];" \
                 : "=r"(r0), "=r"(r1), "=r"(r2), "=r"(r3) : "r"(a))
#define MMA_BF16(d, a, b) \
    asm volatile("mma.sync.aligned.m16n8k16.row.col.f32.bf16.bf16.f32 " \
                 "{%0,%1,%2,%3}, {%4,%5,%6,%7}, {%8,%9}, {%0,%1,%2,%3};" \
                 : "+f"((d)[0]), "+f"((d)[1]), "+f"((d)[2]), "+f"((d)[3]) \
                 : "r"((a)[0]), "r"((a)[1]), "r"((a)[2]), "r"((a)[3]), "r"((b)[0]), "r"((b)[1]))
#define CP_ASYNC16(dst, src) \
    asm volatile("cp.async.cg.shared.global [%0], [%1], 16;" \
                 :: "r"((uint32_t)(dst)), "l"((size_t)__cvta_generic_to_global(src)) : "memory")
#define CP_COMMIT() asm volatile("cp.async.commit_group;" ::: "memory")
#define CP_WAIT0()  asm volatile("cp.async.wait_group 0;" ::: "memory")

// ---- prep: split codebook (h,m) + fp32 bias ---------------------------------
__global__ void prep_kernel(const float* __restrict__ W) {
    int k = blockIdx.x * blockDim.x + threadIdx.x;
    if (k >= NCODE) return;
    float s = 0.0f;
#pragma unroll
    for (int d = 0; d < DIM; d++) {
        float v = W[(size_t)k * DIM + d];
        __nv_bfloat16 h, m;
        split2(v, h, m);
        g_Wsplit[0][k][d] = h; g_Wsplit[1][k][d] = m;
        s = fmaf(v, v, s);
    }
    g_bias[k] = -0.5f * s;
}

// issue cp.async for window w (codes [kbase, kbase+128)), 2 splits
__device__ __forceinline__ void prefetch_win(uint32_t sbase, int w, int kbase, int tid) {
    const char* gw = reinterpret_cast<const char*>(g_Wsplit);
    const uint32_t base = sbase + (((w & 1) == 0) ? SM_BUF1 : 0);
#pragma unroll
    for (int t = 0; t < 8; t++) {
        int i = tid + t * THREADS;                 // 0..2047
        int split = i >> 10, rem = i & 1023;
        int n = rem >> 3, ch = rem & 7;
        uint32_t dst = base + split * SPLIT_W + n * ROWB + ch * 16;
        const char* src = gw + (((size_t)split * NCODE + kbase + n) * 8 + ch) * 16;
        CP_ASYNC16(dst, src);
    }
    if (tid < 32)
        CP_ASYNC16(sbase + SM_BIAS + (w & 1) * 512 + tid * 16,
                   reinterpret_cast<const char*>(g_bias) + (size_t)kbase * 4 + tid * 16);
    CP_COMMIT();
}

// ---- main kernel ------------------------------------------------------------
__global__ __launch_bounds__(THREADS, 2)
void vq_kernel(const float* __restrict__ x,
               const float* __restrict__ W,
               float* __restrict__ out) {
    extern __shared__ char smem[];
    const uint32_t sbase = smem_to_u32(smem);
    const int tid  = threadIdx.x;
    const int lane = tid & 31;
    const int wid  = tid >> 5;
    const int wm   = wid * 16;          // 16 rows per warp

    prefetch_win(sbase, 0, 0, tid);     // window 0 -> dedicated buffer

    // ---- stage A rows into [0, 36864) (h,m splits) ----
    {
        const int row = tid >> 1, half = tid & 1;
        const float4* xr = reinterpret_cast<const float4*>(
            x + ((size_t)blockIdx.x * MCTA + row) * DIM + half * 32);
        char* a0 = smem + row * ROWB + half * 64;
#pragma unroll
        for (int i = 0; i < 8; i++) {
            float4 v = xr[i];
            __nv_bfloat16 h0, m0, h1, m1, h2, m2, h3, m3;
            split2(v.x, h0, m0); split2(v.y, h1, m1);
            split2(v.z, h2, m2); split2(v.w, h3, m3);
            *reinterpret_cast<uint32_t*>(a0 + i * 8)               = pack2(h0, h1);
            *reinterpret_cast<uint32_t*>(a0 + i * 8 + 4)           = pack2(h2, h3);
            *reinterpret_cast<uint32_t*>(a0 + SPLIT_A + i * 8)     = pack2(m0, m1);
            *reinterpret_cast<uint32_t*>(a0 + SPLIT_A + i * 8 + 4) = pack2(m2, m3);
        }
    }
    __syncthreads();

    // ---- A fragments (h,m) -> registers, persistent ----
    uint32_t Af[2][4][4];
    {
        const uint32_t aB = sbase + (uint32_t)(wm + (lane & 15)) * ROWB + (lane >> 4) * 16;
#pragma unroll
        for (int sa = 0; sa < 2; sa++)
#pragma unroll
            for (int k = 0; k < 4; k++)
                LDSM_X4(Af[sa][k][0], Af[sa][k][1], Af[sa][k][2], Af[sa][k][3],
                        aB + sa * SPLIT_A + k * 32);
    }

    // running top-2 per row-chain (q=0: row wm+(lane>>2), q=1: +8)
    float b1[2] = {-3.0e38f, -3.0e38f}, b2[2] = {-3.0e38f, -3.0e38f};
    int   i1[2] = {0, 0},               i2[2] = {1, 1};

    const uint32_t blane = (uint32_t)(((lane >> 4) & 1) * 8 + (lane & 7)) * ROWB
                         + ((lane >> 3) & 1) * 16;

    for (int w = 0; w < NWIN; w++) {
        CP_WAIT0();
        __syncthreads();
        if (w + 1 < NWIN)
            prefetch_win(sbase, w + 1, (w + 1) * WINDOW, tid);

        const uint32_t bufb = sbase + (((w & 1) == 0) ? SM_BUF1 : 0);
        const float* sBias = reinterpret_cast<const float*>(smem + SM_BIAS + (w & 1) * 512);

#pragma unroll
        for (int sc = 0; sc < 2; sc++) {       // two 64-code sub-chunks
            float acc[8][4];
#pragma unroll
            for (int nt = 0; nt < 8; nt++) {
                float2 bb = *reinterpret_cast<const float2*>(
                    &sBias[sc * 64 + nt * 8 + (lane & 3) * 2]);
                acc[nt][0] = bb.x; acc[nt][1] = bb.y;
                acc[nt][2] = bb.x; acc[nt][3] = bb.y;
            }

            const uint32_t bbc = bufb + sc * 64 * ROWB + blane;
#pragma unroll
            for (int k = 0; k < 4; k++) {
#pragma unroll
                for (int np = 0; np < 2; np++) {
                    uint32_t Bh0[4], Bh1[4], Bm0[4], Bm1[4];
                    uint32_t bB = bbc + np * 32 * ROWB + k * 32;
                    LDSM_X4(Bh0[0], Bh0[1], Bh0[2], Bh0[3], bB);
                    LDSM_X4(Bh1[0], Bh1[1], Bh1[2], Bh1[3], bB + 16 * ROWB);
                    LDSM_X4(Bm0[0], Bm0[1], Bm0[2], Bm0[3], bB + SPLIT_W);
                    LDSM_X4(Bm1[0], Bm1[1], Bm1[2], Bm1[3], bB + SPLIT_W + 16 * ROWB);
                    // hh pass
                    MMA_BF16(acc[4 * np + 0], Af[0][k], Bh0);
                    MMA_BF16(acc[4 * np + 1], Af[0][k], Bh0 + 2);
                    MMA_BF16(acc[4 * np + 2], Af[0][k], Bh1);
                    MMA_BF16(acc[4 * np + 3], Af[0][k], Bh1 + 2);
                    // mh pass
                    MMA_BF16(acc[4 * np + 0], Af[1][k], Bh0);
                    MMA_BF16(acc[4 * np + 1], Af[1][k], Bh0 + 2);
                    MMA_BF16(acc[4 * np + 2], Af[1][k], Bh1);
                    MMA_BF16(acc[4 * np + 3], Af[1][k], Bh1 + 2);
                    // hm pass
                    MMA_BF16(acc[4 * np + 0], Af[0][k], Bm0);
                    MMA_BF16(acc[4 * np + 1], Af[0][k], Bm0 + 2);
                    MMA_BF16(acc[4 * np + 2], Af[0][k], Bm1);
                    MMA_BF16(acc[4 * np + 3], Af[0][k], Bm1 + 2);
                }
            }

            // ---- branchless keyed top-2 per chain ----
            const int nbase = w * WINDOW + sc * 64;
#pragma unroll
            for (int q = 0; q < 2; q++) {
                // pair stage: 8 (hi,lo) pairs from 16 keyed elements
                float h[8], l[8];
#pragma unroll
                for (int nt = 0; nt < 8; nt++) {
                    float e0 = embed4(acc[nt][q * 2 + 0], nt * 2 + 0);
                    float e1 = embed4(acc[nt][q * 2 + 1], nt * 2 + 1);
                    h[nt] = fmaxf(e0, e1);
                    l[nt] = fminf(e0, e1);
                }
                // merge tree: top2(u) = (max(h), max(min(h1,h2), max(l1,l2)))
#pragma unroll
                for (int s = 1; s < 8; s <<= 1)
#pragma unroll
                    for (int i = 0; i < 8; i += 2 * s) {
                        float hm = fminf(h[i], h[i + s]);
                        h[i] = fmaxf(h[i], h[i + s]);
                        l[i] = fmaxf(hm, fmaxf(l[i], l[i + s]));
                    }
                // decode two winners
                int lid1 = (int)(__float_as_uint(h[0]) & 15u);
                int lid2 = (int)(__float_as_uint(l[0]) & 15u);
                float v1 = h[0], v2 = l[0];
                int n1 = nbase + (lid1 >> 1) * 8 + (lane & 3) * 2 + (lid1 & 1);
                int n2 = nbase + (lid2 >> 1) * 8 + (lane & 3) * 2 + (lid2 & 1);
                // merge (v1 >= v2) into running top-2 via selects
                bool w1 = v1 > b1[q];
                float c  = w1 ? b1[q] : v1;   int ci  = w1 ? i1[q] : n1;
                float s2 = w1 ? v2    : b2[q]; int s2i = w1 ? n2    : i2[q];
                b1[q] = w1 ? v1 : b1[q];      i1[q] = w1 ? n1 : i1[q];
                bool cw = c > s2;
                b2[q] = cw ? c : s2;          i2[q] = cw ? ci : s2i;
            }
        }
    }

    // ---- quad merge: global top-2 per row across the 4 lanes ----
#pragma unroll
    for (int q = 0; q < 2; q++) {
#pragma unroll
        for (int off = 1; off < 4; off <<= 1) {
            float ob1 = __shfl_xor_sync(0xFFFFFFFFu, b1[q], off);
            int   oi1 = __shfl_xor_sync(0xFFFFFFFFu, i1[q], off);
            float ob2 = __shfl_xor_sync(0xFFFFFFFFu, b2[q], off);
            int   oi2 = __shfl_xor_sync(0xFFFFFFFFu, i2[q], off);
            bool ow = beats(ob1, oi1, b1[q], i1[q]);
            float nv1 = ow ? ob1 : b1[q];  int ni1 = ow ? oi1 : i1[q];
            float cv  = ow ? b1[q] : ob1;  int ci  = ow ? i1[q] : oi1;
            float sv  = ow ? ob2 : b2[q];  int si  = ow ? oi2 : i2[q];
            bool cw = beats(cv, ci, sv, si);
            b1[q] = nv1; i1[q] = ni1;
            b2[q] = cw ? cv : sv; i2[q] = cw ? ci : si;
        }
    }

    // ---- exact fp32 rescore of the two candidates ----
    int Kf[2];
#pragma unroll
    for (int q = 0; q < 2; q++) {
        const int r = wm + (lane >> 2) + q * 8;
        const size_t grow = (size_t)blockIdx.x * MCTA + r;
        const int c1 = i1[q], c2 = i2[q];
        float d1 = 0.0f, d2 = 0.0f;
#pragma unroll
        for (int k = 0; k < 4; k++)
#pragma unroll
            for (int ch = 0; ch < 2; ch++) {
                const int c0 = 2 * (lane & 3) + ch * 8 + 16 * k;
                float2 xx = *reinterpret_cast<const float2*>(x + grow * DIM + c0);
                float2 w1 = __ldg(reinterpret_cast<const float2*>(W + (size_t)c1 * DIM + c0));
                float2 w2 = __ldg(reinterpret_cast<const float2*>(W + (size_t)c2 * DIM + c0));
                d1 = fmaf(xx.x, w1.x, fmaf(xx.y, w1.y, d1));
                d2 = fmaf(xx.x, w2.x, fmaf(xx.y, w2.y, d2));
            }
        d1 += __shfl_xor_sync(0xFFFFFFFFu, d1, 1);
        d1 += __shfl_xor_sync(0xFFFFFFFFu, d1, 2);
        d2 += __shfl_xor_sync(0xFFFFFFFFu, d2, 1);
        d2 += __shfl_xor_sync(0xFFFFFFFFu, d2, 2);
        float s1 = d1 + __ldg(&g_bias[c1]);
        float s2 = d2 + __ldg(&g_bias[c2]);
        Kf[q] = beats(s1, c1, s2, c2) ? c1 : c2;
    }

    // ---- gather codewords + write outputs ----
    const int lq = lane & 3;   // dim slice lq*16 .. lq*16+15
#pragma unroll
    for (int q = 0; q < 2; q++) {
        const int r = wm + (lane >> 2) + q * 8;
        const size_t grow = (size_t)blockIdx.x * MCTA + r;
        const int K = Kf[q];
        const float4* wsrc = reinterpret_cast<const float4*>(W + (size_t)K * DIM + lq * 16);
        float4* o1 = reinterpret_cast<float4*>(out + grow * DIM + lq * 16);
        float4* o2 = reinterpret_cast<float4*>(out + ((size_t)NROWS + grow) * DIM + lq * 16);
#pragma unroll
        for (int i = 0; i < 4; i++) {
            float4 v = wsrc[i];
            o1[i] = v;
            o2[i] = v;
        }
        if (lq == 0)
            out[(size_t)2 * NROWS * DIM + grow] = (float)K;
    }
}

// ---- launch -----------------------------------------------------------------
extern "C" void kernel_launch(void* const* d_in, const int* in_sizes, int n_in,
                              void* d_out, int out_size) {
    const float* x = (const float*)d_in[0];
    const float* W = (const float*)d_in[1];
    float* out = (float*)d_out;

    cudaFuncSetAttribute(vq_kernel, cudaFuncAttributeMaxDynamicSharedMemorySize, SMEM_TOTAL);
    prep_kernel<<<NCODE / 256, 256>>>(W);
    vq_kernel<<<NROWS / MCTA, THREADS, SMEM_TOTAL>>>(x, W, out);
}